// round 2
// baseline (speedup 1.0000x reference)
#include <cuda_runtime.h>

#define NN 50000
#define EE 800000
#define KIN 256
#define HD  256
#define NH  4

// ---------------- static scratch (no runtime allocation) ----------------
__device__ float g_feat0[(size_t)NN * HD];
__device__ float g_feat1[(size_t)NN * HD];
__device__ float g_o0[(size_t)NN * HD];
__device__ float g_o1[(size_t)NN * HD];
__device__ float g_el[2][NN * NH];
__device__ float g_er[2][NN * NH];
__device__ float g_Wtg[KIN * 512];      // [k][n] n<256 -> Wg1, else Wg2
__device__ float g_Wtfc[512 * HD];      // [k][n]
__device__ float g_bfceff[HD];
__device__ int   g_deg[2][NN];
__device__ int   g_rowptr[2][NN + 1];
__device__ int   g_cur[2][NN];
__device__ int   g_csrc[2][EE];

// ---------------- helpers ----------------
__device__ __forceinline__ unsigned long long packf2(float x, float y) {
    unsigned long long r;
    asm("mov.b64 %0, {%1,%2};" : "=l"(r) : "f"(x), "f"(y));
    return r;
}
__device__ __forceinline__ void fma2(unsigned long long& c, unsigned long long a, unsigned long long b) {
    asm("fma.rn.f32x2 %0, %1, %2, %0;" : "+l"(c) : "l"(a), "l"(b));
}
__device__ __forceinline__ float2 unpackf2(unsigned long long v) {
    float2 r;
    asm("mov.b64 {%0,%1}, %2;" : "=f"(r.x), "=f"(r.y) : "l"(v));
    return r;
}
__device__ __forceinline__ float lrelu(float x) { return x > 0.0f ? x : 0.2f * x; }
__device__ __forceinline__ float pick4(float4 v, int h) {
    float ab = (h == 0) ? v.x : v.y;
    float cd = (h == 2) ? v.z : v.w;
    return (h < 2) ? ab : cd;
}

// ---------------- prep: weight transposes + zero degree counters ----------------
__global__ void k_prep(const float* __restrict__ Wg1, const float* __restrict__ Wg2,
                       const float* __restrict__ Wfc) {
    int i = blockIdx.x * blockDim.x + threadIdx.x;
    if (i < KIN * 512) {
        int k = i >> 9, n = i & 511;
        g_Wtg[i] = (n < HD) ? Wg1[n * KIN + k] : Wg2[(n - HD) * KIN + k];
    } else {
        int j = i - KIN * 512;
        if (j < 512 * HD) {
            int k = j >> 8, n = j & 255;
            g_Wtfc[j] = Wfc[n * 512 + k];
        } else {
            int t = j - 512 * HD;
            if (t < 2 * NN) ((int*)g_deg)[t] = 0;
        }
    }
}

// effective FC bias: bfc + Wfc @ concat(b1,b2)
__global__ void k_bfc(const float* __restrict__ b1, const float* __restrict__ b2,
                      const float* __restrict__ Wfc, const float* __restrict__ bfc) {
    int i = threadIdx.x;
    float s = bfc[i];
    const float* w = Wfc + (size_t)i * 512;
    for (int j = 0; j < HD; j++) s += w[j] * b1[j];
    for (int j = 0; j < HD; j++) s += w[HD + j] * b2[j];
    g_bfceff[i] = s;
}

// ---------------- GEMM 1: feat = h @ Wg^T (both relations fused, Nc=512) ----------------
__global__ void __launch_bounds__(256) k_gemm_feat(const float* __restrict__ A) {
    __shared__ float As[8][128];
    __shared__ float Bs[8][128];
    int tid = threadIdx.x;
    int row0 = blockIdx.y * 128, col0 = blockIdx.x * 128;
    int aRow = tid >> 1, aCol = (tid & 1) * 4;
    int bRow = tid >> 5, bCol = (tid & 31) * 4;
    int tx = tid & 15, ty = tid >> 4;
    unsigned long long acc[8][4];
#pragma unroll
    for (int i = 0; i < 8; i++)
#pragma unroll
        for (int j = 0; j < 4; j++) acc[i][j] = 0ull;

    for (int k0 = 0; k0 < KIN; k0 += 8) {
        int gr = row0 + aRow;
        float4 av = make_float4(0.f, 0.f, 0.f, 0.f);
        if (gr < NN) av = *(const float4*)(A + (size_t)gr * KIN + k0 + aCol);
        As[aCol + 0][aRow] = av.x; As[aCol + 1][aRow] = av.y;
        As[aCol + 2][aRow] = av.z; As[aCol + 3][aRow] = av.w;
        *(float4*)&Bs[bRow][bCol] = *(const float4*)(g_Wtg + (size_t)(k0 + bRow) * 512 + col0 + bCol);
        __syncthreads();
#pragma unroll
        for (int kk = 0; kk < 8; kk++) {
            float4 a0 = *(const float4*)&As[kk][ty * 8];
            float4 a1 = *(const float4*)&As[kk][ty * 8 + 4];
            float4 b0 = *(const float4*)&Bs[kk][tx * 8];
            float4 b1 = *(const float4*)&Bs[kk][tx * 8 + 4];
            unsigned long long bb[4] = {packf2(b0.x, b0.y), packf2(b0.z, b0.w),
                                        packf2(b1.x, b1.y), packf2(b1.z, b1.w)};
            float aa[8] = {a0.x, a0.y, a0.z, a0.w, a1.x, a1.y, a1.z, a1.w};
#pragma unroll
            for (int i = 0; i < 8; i++) {
                unsigned long long ad = packf2(aa[i], aa[i]);
#pragma unroll
                for (int j = 0; j < 4; j++) fma2(acc[i][j], ad, bb[j]);
            }
        }
        __syncthreads();
    }
    float* Cb; int cc;
    if (col0 < 256) { Cb = g_feat0; cc = col0; } else { Cb = g_feat1; cc = col0 - 256; }
#pragma unroll
    for (int i = 0; i < 8; i++) {
        int gr = row0 + ty * 8 + i;
        if (gr < NN) {
            float2 p0 = unpackf2(acc[i][0]), p1 = unpackf2(acc[i][1]);
            float2 p2 = unpackf2(acc[i][2]), p3 = unpackf2(acc[i][3]);
            float4 v0 = make_float4(p0.x, p0.y, p1.x, p1.y);
            float4 v1 = make_float4(p2.x, p2.y, p3.x, p3.y);
            *(float4*)(Cb + (size_t)gr * HD + cc + tx * 8) = v0;
            *(float4*)(Cb + (size_t)gr * HD + cc + tx * 8 + 4) = v1;
        }
    }
}

// ---------------- per-node attention coefficients el/er ----------------
__global__ void k_eler(const float* __restrict__ al1, const float* __restrict__ ar1,
                       const float* __restrict__ al2, const float* __restrict__ ar2) {
    int gw = (blockIdx.x * blockDim.x + threadIdx.x) >> 5;
    int lane = threadIdx.x & 31;
    int r = gw & 1, n = gw >> 1;
    if (n >= NN) return;
    const float* f = (r ? g_feat1 : g_feat0) + (size_t)n * HD + lane * 8;
    int off = (lane >> 3) * 64 + (lane & 7) * 8;
    const float* al = (r ? al2 : al1) + off;
    const float* ar = (r ? ar2 : ar1) + off;
    float4 f0 = *(const float4*)f, f1 = *(const float4*)(f + 4);
    float4 l0 = *(const float4*)al, l1 = *(const float4*)(al + 4);
    float4 r0 = *(const float4*)ar, r1 = *(const float4*)(ar + 4);
    float sl = f0.x * l0.x + f0.y * l0.y + f0.z * l0.z + f0.w * l0.w
             + f1.x * l1.x + f1.y * l1.y + f1.z * l1.z + f1.w * l1.w;
    float sr = f0.x * r0.x + f0.y * r0.y + f0.z * r0.z + f0.w * r0.w
             + f1.x * r1.x + f1.y * r1.y + f1.z * r1.z + f1.w * r1.w;
#pragma unroll
    for (int s = 4; s >= 1; s >>= 1) {
        sl += __shfl_xor_sync(0xffffffffu, sl, s);
        sr += __shfl_xor_sync(0xffffffffu, sr, s);
    }
    if ((lane & 7) == 0) {
        int h = lane >> 3;
        g_el[r][n * NH + h] = sl;
        g_er[r][n * NH + h] = sr;
    }
}

// ---------------- CSR build ----------------
__global__ void k_count(const int* __restrict__ d1, const int* __restrict__ d2) {
    int e = blockIdx.x * blockDim.x + threadIdx.x;
    int r = blockIdx.y;
    if (e >= EE) return;
    const int* Dd = r ? d2 : d1;
    atomicAdd(&g_deg[r][Dd[e]], 1);
}

__global__ void k_scan() {
    int r = blockIdx.x;
    __shared__ int s_w[32];
    __shared__ int s_tot;
    int lane = threadIdx.x & 31, wid = threadIdx.x >> 5;
    int running = 0;
    for (int base = 0; base < NN; base += 1024) {
        int i = base + threadIdx.x;
        int v = (i < NN) ? g_deg[r][i] : 0;
        int x = v;
#pragma unroll
        for (int s = 1; s < 32; s <<= 1) {
            int y = __shfl_up_sync(0xffffffffu, x, s);
            if (lane >= s) x += y;
        }
        if (lane == 31) s_w[wid] = x;
        __syncthreads();
        if (wid == 0) {
            int t = s_w[lane];
            int xs = t;
#pragma unroll
            for (int s = 1; s < 32; s <<= 1) {
                int y = __shfl_up_sync(0xffffffffu, xs, s);
                if (lane >= s) xs += y;
            }
            s_w[lane] = xs - t;
            if (lane == 31) s_tot = xs;
        }
        __syncthreads();
        if (i < NN) g_rowptr[r][i] = running + s_w[wid] + x - v;
        running += s_tot;
        __syncthreads();
    }
    if (threadIdx.x == 0) g_rowptr[r][NN] = running;
}

__global__ void k_cursor() {
    int t = blockIdx.x * blockDim.x + threadIdx.x;
    if (t < 2 * NN) {
        int r = t / NN, i = t - r * NN;
        g_cur[r][i] = g_rowptr[r][i];
    }
}

__global__ void k_scatter(const int* __restrict__ s1, const int* __restrict__ d1,
                          const int* __restrict__ s2, const int* __restrict__ d2) {
    int e = blockIdx.x * blockDim.x + threadIdx.x;
    int r = blockIdx.y;
    if (e >= EE) return;
    const int* S = r ? s2 : s1;
    const int* Dd = r ? d2 : d1;
    int d = Dd[e];
    int pos = atomicAdd(&g_cur[r][d], 1);
    g_csrc[r][pos] = S[e];
}

// ---------------- node-centric softmax + gather (one warp per node) ----------------
__global__ void __launch_bounds__(256) k_node() {
    int gw = (blockIdx.x * 256 + threadIdx.x) >> 5;
    int lane = threadIdx.x & 31;
    int r = blockIdx.y;
    int n = gw;
    if (n >= NN) return;
    int start = g_rowptr[r][n], end = g_rowptr[r][n + 1];
    const float* el = g_el[r];
    float4 er4 = *(const float4*)(&g_er[r][n * NH]);
    const int* csrc = g_csrc[r];
    const float* feat = r ? g_feat1 : g_feat0;

    // pass 1: per-head max
    float4 m = make_float4(-3.0e38f, -3.0e38f, -3.0e38f, -3.0e38f);
    for (int i = start + lane; i < end; i += 32) {
        int s = csrc[i];
        float4 e4 = *(const float4*)(el + s * NH);
        m.x = fmaxf(m.x, lrelu(e4.x + er4.x));
        m.y = fmaxf(m.y, lrelu(e4.y + er4.y));
        m.z = fmaxf(m.z, lrelu(e4.z + er4.z));
        m.w = fmaxf(m.w, lrelu(e4.w + er4.w));
    }
#pragma unroll
    for (int s = 16; s >= 1; s >>= 1) {
        m.x = fmaxf(m.x, __shfl_xor_sync(0xffffffffu, m.x, s));
        m.y = fmaxf(m.y, __shfl_xor_sync(0xffffffffu, m.y, s));
        m.z = fmaxf(m.z, __shfl_xor_sync(0xffffffffu, m.z, s));
        m.w = fmaxf(m.w, __shfl_xor_sync(0xffffffffu, m.w, s));
    }
    // pass 2: per-head denom
    float4 dn = make_float4(0.f, 0.f, 0.f, 0.f);
    for (int i = start + lane; i < end; i += 32) {
        int s = csrc[i];
        float4 e4 = *(const float4*)(el + s * NH);
        dn.x += __expf(lrelu(e4.x + er4.x) - m.x);
        dn.y += __expf(lrelu(e4.y + er4.y) - m.y);
        dn.z += __expf(lrelu(e4.z + er4.z) - m.z);
        dn.w += __expf(lrelu(e4.w + er4.w) - m.w);
    }
#pragma unroll
    for (int s = 16; s >= 1; s >>= 1) {
        dn.x += __shfl_xor_sync(0xffffffffu, dn.x, s);
        dn.y += __shfl_xor_sync(0xffffffffu, dn.y, s);
        dn.z += __shfl_xor_sync(0xffffffffu, dn.z, s);
        dn.w += __shfl_xor_sync(0xffffffffu, dn.w, s);
    }
    float4 inv = make_float4(dn.x > 0.f ? 1.f / dn.x : 0.f,
                             dn.y > 0.f ? 1.f / dn.y : 0.f,
                             dn.z > 0.f ? 1.f / dn.z : 0.f,
                             dn.w > 0.f ? 1.f / dn.w : 0.f);
    int head = lane >> 3;
    float erh = pick4(er4, head);
    float mh = pick4(m, head);
    float ih = pick4(inv, head);
    float acc[8] = {0.f, 0.f, 0.f, 0.f, 0.f, 0.f, 0.f, 0.f};
    // pass 3: weighted gather (all lanes walk all edges together)
    for (int i = start; i < end; i++) {
        int s = csrc[i];
        float4 e4 = *(const float4*)(el + s * NH);
        float a = __expf(lrelu(pick4(e4, head) + erh) - mh) * ih;
        const float* f = feat + (size_t)s * HD + lane * 8;
        float4 f0 = *(const float4*)f, f1 = *(const float4*)(f + 4);
        acc[0] += a * f0.x; acc[1] += a * f0.y; acc[2] += a * f0.z; acc[3] += a * f0.w;
        acc[4] += a * f1.x; acc[5] += a * f1.y; acc[6] += a * f1.z; acc[7] += a * f1.w;
    }
    float* o = (r ? g_o1 : g_o0) + (size_t)n * HD + lane * 8;
    *(float4*)o = make_float4(acc[0], acc[1], acc[2], acc[3]);
    *(float4*)(o + 4) = make_float4(acc[4], acc[5], acc[6], acc[7]);
}

// ---------------- GEMM 2: out = [o1 o2] @ Wfc^T + bfc_eff ----------------
__global__ void __launch_bounds__(256) k_gemm_out(float* __restrict__ C) {
    __shared__ float As[8][128];
    __shared__ float Bs[8][128];
    int tid = threadIdx.x;
    int row0 = blockIdx.y * 128, col0 = blockIdx.x * 128;
    int aRow = tid >> 1, aCol = (tid & 1) * 4;
    int bRow = tid >> 5, bCol = (tid & 31) * 4;
    int tx = tid & 15, ty = tid >> 4;
    unsigned long long acc[8][4];
#pragma unroll
    for (int i = 0; i < 8; i++)
#pragma unroll
        for (int j = 0; j < 4; j++) acc[i][j] = 0ull;

    for (int k0 = 0; k0 < 512; k0 += 8) {
        int gr = row0 + aRow;
        int kk = k0 + aCol;
        float4 av = make_float4(0.f, 0.f, 0.f, 0.f);
        if (gr < NN) {
            const float* Ab = (kk < HD) ? (g_o0 + (size_t)gr * HD + kk)
                                        : (g_o1 + (size_t)gr * HD + (kk - HD));
            av = *(const float4*)Ab;
        }
        As[aCol + 0][aRow] = av.x; As[aCol + 1][aRow] = av.y;
        As[aCol + 2][aRow] = av.z; As[aCol + 3][aRow] = av.w;
        *(float4*)&Bs[bRow][bCol] = *(const float4*)(g_Wtfc + (size_t)(k0 + bRow) * HD + col0 + bCol);
        __syncthreads();
#pragma unroll
        for (int kq = 0; kq < 8; kq++) {
            float4 a0 = *(const float4*)&As[kq][ty * 8];
            float4 a1 = *(const float4*)&As[kq][ty * 8 + 4];
            float4 b0 = *(const float4*)&Bs[kq][tx * 8];
            float4 b1 = *(const float4*)&Bs[kq][tx * 8 + 4];
            unsigned long long bb[4] = {packf2(b0.x, b0.y), packf2(b0.z, b0.w),
                                        packf2(b1.x, b1.y), packf2(b1.z, b1.w)};
            float aa[8] = {a0.x, a0.y, a0.z, a0.w, a1.x, a1.y, a1.z, a1.w};
#pragma unroll
            for (int i = 0; i < 8; i++) {
                unsigned long long ad = packf2(aa[i], aa[i]);
#pragma unroll
                for (int j = 0; j < 4; j++) fma2(acc[i][j], ad, bb[j]);
            }
        }
        __syncthreads();
    }
#pragma unroll
    for (int i = 0; i < 8; i++) {
        int gr = row0 + ty * 8 + i;
        if (gr < NN) {
            int cb = col0 + tx * 8;
            float2 p0 = unpackf2(acc[i][0]), p1 = unpackf2(acc[i][1]);
            float2 p2 = unpackf2(acc[i][2]), p3 = unpackf2(acc[i][3]);
            float4 v0 = make_float4(p0.x + g_bfceff[cb + 0], p0.y + g_bfceff[cb + 1],
                                    p1.x + g_bfceff[cb + 2], p1.y + g_bfceff[cb + 3]);
            float4 v1 = make_float4(p2.x + g_bfceff[cb + 4], p2.y + g_bfceff[cb + 5],
                                    p3.x + g_bfceff[cb + 6], p3.y + g_bfceff[cb + 7]);
            *(float4*)(C + (size_t)gr * HD + cb) = v0;
            *(float4*)(C + (size_t)gr * HD + cb + 4) = v1;
        }
    }
}

// ---------------- launch ----------------
extern "C" void kernel_launch(void* const* d_in, const int* in_sizes, int n_in,
                              void* d_out, int out_size) {
    const float* h   = (const float*)d_in[0];
    const float* Wg1 = (const float*)d_in[1];
    const float* al1 = (const float*)d_in[2];
    const float* ar1 = (const float*)d_in[3];
    const float* b1  = (const float*)d_in[4];
    const float* Wg2 = (const float*)d_in[5];
    const float* al2 = (const float*)d_in[6];
    const float* ar2 = (const float*)d_in[7];
    const float* b2  = (const float*)d_in[8];
    const float* Wfc = (const float*)d_in[9];
    const float* bfc = (const float*)d_in[10];
    const int* src1  = (const int*)d_in[11];
    const int* dst1  = (const int*)d_in[12];
    const int* src2  = (const int*)d_in[13];
    const int* dst2  = (const int*)d_in[14];
    float* out = (float*)d_out;

    int prep_total = KIN * 512 + 512 * HD + 2 * NN;
    k_prep<<<(prep_total + 255) / 256, 256>>>(Wg1, Wg2, Wfc);
    k_bfc<<<1, 256>>>(b1, b2, Wfc, bfc);

    dim3 g1(4, (NN + 127) / 128);
    k_gemm_feat<<<g1, 256>>>(h);

    k_eler<<<(2 * NN + 7) / 8, 256>>>(al1, ar1, al2, ar2);

    dim3 ge((EE + 255) / 256, 2);
    k_count<<<ge, 256>>>(dst1, dst2);
    k_scan<<<2, 1024>>>();
    k_cursor<<<(2 * NN + 255) / 256, 256>>>();
    k_scatter<<<ge, 256>>>(src1, dst1, src2, dst2);

    dim3 gn((NN + 7) / 8, 2);
    k_node<<<gn, 256>>>();

    dim3 g2(2, (NN + 127) / 128);
    k_gemm_out<<<g2, 256>>>(out);
}

// round 5
// speedup vs baseline: 1.5138x; 1.5138x over previous
#include <cuda_runtime.h>
#include <cstdint>

#define NN 50000
#define EE 800000
#define KIN 256
#define HD  256
#define NH  4

// ---------------- static scratch (no runtime allocation) ----------------
__device__ float g_feat0[(size_t)NN * HD];
__device__ float g_feat1[(size_t)NN * HD];
__device__ float g_o0[(size_t)NN * HD];
__device__ float g_o1[(size_t)NN * HD];
__device__ float g_el[2][NN * NH];
__device__ float g_er[2][NN * NH];
__device__ float g_bfceff[HD];
__device__ int   g_deg[2][NN];
__device__ int   g_rowptr[2][NN + 1];
__device__ int   g_cur[2][NN];
__device__ int   g_csrc[2][EE];

// ---------------- helpers ----------------
__device__ __forceinline__ float tf32r(float x) {
    uint32_t r; asm("cvt.rna.tf32.f32 %0, %1;" : "=r"(r) : "f"(x));
    return __uint_as_float(r);
}
__device__ __forceinline__ void mma8(float& c0, float& c1, float& c2, float& c3,
                                     float a0, float a1, float a2, float a3,
                                     float b0, float b1) {
    asm volatile(
        "mma.sync.aligned.m16n8k8.row.col.f32.tf32.tf32.f32 "
        "{%0,%1,%2,%3}, {%4,%5,%6,%7}, {%8,%9}, {%0,%1,%2,%3};"
        : "+f"(c0), "+f"(c1), "+f"(c2), "+f"(c3)
        : "r"(__float_as_uint(a0)), "r"(__float_as_uint(a1)),
          "r"(__float_as_uint(a2)), "r"(__float_as_uint(a3)),
          "r"(__float_as_uint(b0)), "r"(__float_as_uint(b1)));
}
__device__ __forceinline__ float lrelu(float x) { return x > 0.0f ? x : 0.2f * x; }
__device__ __forceinline__ float pick4(float4 v, int h) {
    float ab = (h == 0) ? v.x : v.y;
    float cd = (h == 2) ? v.z : v.w;
    return (h < 2) ? ab : cd;
}

// ================= GEMM1: feat_r = h @ Wg_r^T, fused el/er =================
// CTA tile 128x128, BK=16, 128 threads, 2x2 warps of 64x64.
// grid = (4, ceil(NN/128)); bx 0..1 -> rel0 (Wg1), bx 2..3 -> rel1 (Wg2).
__global__ void __launch_bounds__(128, 2) k_gemm1(
    const float* __restrict__ h,
    const float* __restrict__ Wg1, const float* __restrict__ Wg2,
    const float* __restrict__ al1, const float* __restrict__ arr1,
    const float* __restrict__ al2, const float* __restrict__ arr2)
{
    __shared__ float As[16][136];
    __shared__ float Bs[16][136];
    const int tid = threadIdx.x;
    const int bx = blockIdx.x, by = blockIdx.y;
    const int rel = bx >> 1;
    const int nbase = (bx & 1) * 128;
    const float* Bmat = rel ? Wg2 : Wg1;

    const int lane = tid & 31, warp = tid >> 5;
    const int wr = warp >> 1, wc = warp & 1;
    const int g = lane >> 2, tig = lane & 3;

    const int arow = by * 128 + tid;
    const bool av = arow < NN;
    const float* Aptr = h + (size_t)arow * KIN;
    const float* Bptr = Bmat + (size_t)(nbase + tid) * KIN;

    float4 sa[4], sb[4];
#pragma unroll
    for (int i = 0; i < 4; i++) {
        sa[i] = av ? *(const float4*)(Aptr + i * 4) : make_float4(0.f, 0.f, 0.f, 0.f);
        sb[i] = *(const float4*)(Bptr + i * 4);
    }

    float c[4][8][4];
#pragma unroll
    for (int mt = 0; mt < 4; mt++)
#pragma unroll
        for (int nt = 0; nt < 8; nt++)
#pragma unroll
            for (int q = 0; q < 4; q++) c[mt][nt][q] = 0.f;

    const int NC = KIN / 16;  // 16
    for (int ck = 0; ck < NC; ck++) {
#pragma unroll
        for (int i = 0; i < 4; i++) {
            As[i * 4 + 0][tid] = tf32r(sa[i].x); As[i * 4 + 1][tid] = tf32r(sa[i].y);
            As[i * 4 + 2][tid] = tf32r(sa[i].z); As[i * 4 + 3][tid] = tf32r(sa[i].w);
            Bs[i * 4 + 0][tid] = tf32r(sb[i].x); Bs[i * 4 + 1][tid] = tf32r(sb[i].y);
            Bs[i * 4 + 2][tid] = tf32r(sb[i].z); Bs[i * 4 + 3][tid] = tf32r(sb[i].w);
        }
        __syncthreads();
        if (ck + 1 < NC) {
            const float* ap = Aptr + (ck + 1) * 16;
            const float* bp = Bptr + (ck + 1) * 16;
#pragma unroll
            for (int i = 0; i < 4; i++) {
                sa[i] = av ? *(const float4*)(ap + i * 4) : make_float4(0.f, 0.f, 0.f, 0.f);
                sb[i] = *(const float4*)(bp + i * 4);
            }
        }
#pragma unroll
        for (int k8 = 0; k8 < 16; k8 += 8) {
            float bf[8][2];
#pragma unroll
            for (int nt = 0; nt < 8; nt++) {
                bf[nt][0] = Bs[k8 + tig][wc * 64 + nt * 8 + g];
                bf[nt][1] = Bs[k8 + tig + 4][wc * 64 + nt * 8 + g];
            }
#pragma unroll
            for (int mt = 0; mt < 4; mt++) {
                int mb = wr * 64 + mt * 16 + g;
                float a0 = As[k8 + tig][mb];
                float a1 = As[k8 + tig][mb + 8];
                float a2 = As[k8 + tig + 4][mb];
                float a3 = As[k8 + tig + 4][mb + 8];
#pragma unroll
                for (int nt = 0; nt < 8; nt++)
                    mma8(c[mt][nt][0], c[mt][nt][1], c[mt][nt][2], c[mt][nt][3],
                         a0, a1, a2, a3, bf[nt][0], bf[nt][1]);
            }
        }
        __syncthreads();
    }

    // ---------------- epilogue: write feat + fused el/er ----------------
    const int hloc = (bx & 1) * 2 + wc;
    const float* alp = (rel ? al2 : al1) + hloc * 64;
    const float* arp = (rel ? arr2 : arr1) + hloc * 64;
    float* feat = rel ? g_feat1 : g_feat0;

    float els[8], ers[8];
#pragma unroll
    for (int i = 0; i < 8; i++) { els[i] = 0.f; ers[i] = 0.f; }

#pragma unroll
    for (int mt = 0; mt < 4; mt++) {
#pragma unroll
        for (int nt = 0; nt < 8; nt++) {
            int d0 = nt * 8 + 2 * tig;
            float w0 = alp[d0], w1 = alp[d0 + 1];
            float v0 = arp[d0], v1 = arp[d0 + 1];
            els[mt * 2 + 0] += c[mt][nt][0] * w0 + c[mt][nt][1] * w1;
            ers[mt * 2 + 0] += c[mt][nt][0] * v0 + c[mt][nt][1] * v1;
            els[mt * 2 + 1] += c[mt][nt][2] * w0 + c[mt][nt][3] * w1;
            ers[mt * 2 + 1] += c[mt][nt][2] * v0 + c[mt][nt][3] * v1;
        }
    }
#pragma unroll
    for (int i = 0; i < 8; i++) {
#pragma unroll
        for (int s = 1; s <= 2; s <<= 1) {
            els[i] += __shfl_xor_sync(0xffffffffu, els[i], s);
            ers[i] += __shfl_xor_sync(0xffffffffu, ers[i], s);
        }
    }

#pragma unroll
    for (int mt = 0; mt < 4; mt++) {
        int r0 = by * 128 + wr * 64 + mt * 16 + g;
        int r1 = r0 + 8;
        if (r0 < NN) {
            float* fb = feat + (size_t)r0 * HD + nbase + wc * 64 + 2 * tig;
#pragma unroll
            for (int nt = 0; nt < 8; nt++)
                *(float2*)(fb + nt * 8) = make_float2(c[mt][nt][0], c[mt][nt][1]);
            if (tig == 0) {
                g_el[rel][r0 * NH + hloc] = els[mt * 2 + 0];
                g_er[rel][r0 * NH + hloc] = ers[mt * 2 + 0];
            }
        }
        if (r1 < NN) {
            float* fb = feat + (size_t)r1 * HD + nbase + wc * 64 + 2 * tig;
#pragma unroll
            for (int nt = 0; nt < 8; nt++)
                *(float2*)(fb + nt * 8) = make_float2(c[mt][nt][2], c[mt][nt][3]);
            if (tig == 0) {
                g_el[rel][r1 * NH + hloc] = els[mt * 2 + 1];
                g_er[rel][r1 * NH + hloc] = ers[mt * 2 + 1];
            }
        }
    }
}

// ================= GEMM2: out = [o0 o1] @ Wfc^T + bfc_eff =================
// grid = (2, ceil(NN/128)); K = 512 (first 256 from o0, rest from o1).
__global__ void __launch_bounds__(128, 2) k_gemm2(const float* __restrict__ Wfc,
                                                  float* __restrict__ C)
{
    __shared__ float As[16][136];
    __shared__ float Bs[16][136];
    const int tid = threadIdx.x;
    const int bx = blockIdx.x, by = blockIdx.y;
    const int nbase = bx * 128;

    const int lane = tid & 31, warp = tid >> 5;
    const int wr = warp >> 1, wc = warp & 1;
    const int g = lane >> 2, tig = lane & 3;

    const int arow = by * 128 + tid;
    const bool av = arow < NN;
    const float* Bptr = Wfc + (size_t)(nbase + tid) * 512;

    float4 sa[4], sb[4];
    {
        const float* ap = g_o0 + (size_t)arow * HD;
#pragma unroll
        for (int i = 0; i < 4; i++) {
            sa[i] = av ? *(const float4*)(ap + i * 4) : make_float4(0.f, 0.f, 0.f, 0.f);
            sb[i] = *(const float4*)(Bptr + i * 4);
        }
    }

    float c[4][8][4];
#pragma unroll
    for (int mt = 0; mt < 4; mt++)
#pragma unroll
        for (int nt = 0; nt < 8; nt++)
#pragma unroll
            for (int q = 0; q < 4; q++) c[mt][nt][q] = 0.f;

    const int NC = 512 / 16;  // 32
    for (int ck = 0; ck < NC; ck++) {
#pragma unroll
        for (int i = 0; i < 4; i++) {
            As[i * 4 + 0][tid] = tf32r(sa[i].x); As[i * 4 + 1][tid] = tf32r(sa[i].y);
            As[i * 4 + 2][tid] = tf32r(sa[i].z); As[i * 4 + 3][tid] = tf32r(sa[i].w);
            Bs[i * 4 + 0][tid] = tf32r(sb[i].x); Bs[i * 4 + 1][tid] = tf32r(sb[i].y);
            Bs[i * 4 + 2][tid] = tf32r(sb[i].z); Bs[i * 4 + 3][tid] = tf32r(sb[i].w);
        }
        __syncthreads();
        if (ck + 1 < NC) {
            int k0 = (ck + 1) * 16;
            const float* ap = (k0 < HD) ? (g_o0 + (size_t)arow * HD + k0)
                                        : (g_o1 + (size_t)arow * HD + (k0 - HD));
            const float* bp = Bptr + k0;
#pragma unroll
            for (int i = 0; i < 4; i++) {
                sa[i] = av ? *(const float4*)(ap + i * 4) : make_float4(0.f, 0.f, 0.f, 0.f);
                sb[i] = *(const float4*)(bp + i * 4);
            }
        }
#pragma unroll
        for (int k8 = 0; k8 < 16; k8 += 8) {
            float bf[8][2];
#pragma unroll
            for (int nt = 0; nt < 8; nt++) {
                bf[nt][0] = Bs[k8 + tig][wc * 64 + nt * 8 + g];
                bf[nt][1] = Bs[k8 + tig + 4][wc * 64 + nt * 8 + g];
            }
#pragma unroll
            for (int mt = 0; mt < 4; mt++) {
                int mb = wr * 64 + mt * 16 + g;
                float a0 = As[k8 + tig][mb];
                float a1 = As[k8 + tig][mb + 8];
                float a2 = As[k8 + tig + 4][mb];
                float a3 = As[k8 + tig + 4][mb + 8];
#pragma unroll
                for (int nt = 0; nt < 8; nt++)
                    mma8(c[mt][nt][0], c[mt][nt][1], c[mt][nt][2], c[mt][nt][3],
                         a0, a1, a2, a3, bf[nt][0], bf[nt][1]);
            }
        }
        __syncthreads();
    }

#pragma unroll
    for (int mt = 0; mt < 4; mt++) {
        int r0 = by * 128 + wr * 64 + mt * 16 + g;
        int r1 = r0 + 8;
        int cb = nbase + wc * 64 + 2 * tig;
        if (r0 < NN) {
            float* ob = C + (size_t)r0 * HD + cb;
#pragma unroll
            for (int nt = 0; nt < 8; nt++)
                *(float2*)(ob + nt * 8) = make_float2(c[mt][nt][0] + g_bfceff[cb + nt * 8],
                                                      c[mt][nt][1] + g_bfceff[cb + nt * 8 + 1]);
        }
        if (r1 < NN) {
            float* ob = C + (size_t)r1 * HD + cb;
#pragma unroll
            for (int nt = 0; nt < 8; nt++)
                *(float2*)(ob + nt * 8) = make_float2(c[mt][nt][2] + g_bfceff[cb + nt * 8],
                                                      c[mt][nt][3] + g_bfceff[cb + nt * 8 + 1]);
        }
    }
}

// ---------------- misc small kernels ----------------
__global__ void k_zero() {
    int t = blockIdx.x * blockDim.x + threadIdx.x;
    if (t < 2 * NN) ((int*)g_deg)[t] = 0;
}

__global__ void k_bfc(const float* __restrict__ b1, const float* __restrict__ b2,
                      const float* __restrict__ Wfc, const float* __restrict__ bfc) {
    int i = threadIdx.x;
    float s = bfc[i];
    const float* w = Wfc + (size_t)i * 512;
    for (int j = 0; j < HD; j++) s += w[j] * b1[j];
    for (int j = 0; j < HD; j++) s += w[HD + j] * b2[j];
    g_bfceff[i] = s;
}

// ---------------- CSR build ----------------
__global__ void k_count(const int* __restrict__ d1, const int* __restrict__ d2) {
    int e = blockIdx.x * blockDim.x + threadIdx.x;
    int r = blockIdx.y;
    if (e >= EE) return;
    const int* Dd = r ? d2 : d1;
    atomicAdd(&g_deg[r][Dd[e]], 1);
}

__global__ void k_scan() {
    int r = blockIdx.x;
    __shared__ int s_w[32];
    __shared__ int s_tot;
    int lane = threadIdx.x & 31, wid = threadIdx.x >> 5;
    int running = 0;
    for (int base = 0; base < NN; base += 1024) {
        int i = base + threadIdx.x;
        int v = (i < NN) ? g_deg[r][i] : 0;
        int x = v;
#pragma unroll
        for (int s = 1; s < 32; s <<= 1) {
            int y = __shfl_up_sync(0xffffffffu, x, s);
            if (lane >= s) x += y;
        }
        if (lane == 31) s_w[wid] = x;
        __syncthreads();
        if (wid == 0) {
            int t = s_w[lane];
            int xs = t;
#pragma unroll
            for (int s = 1; s < 32; s <<= 1) {
                int y = __shfl_up_sync(0xffffffffu, xs, s);
                if (lane >= s) xs += y;
            }
            s_w[lane] = xs - t;
            if (lane == 31) s_tot = xs;
        }
        __syncthreads();
        if (i < NN) g_rowptr[r][i] = running + s_w[wid] + x - v;
        running += s_tot;
        __syncthreads();
    }
    if (threadIdx.x == 0) g_rowptr[r][NN] = running;
}

__global__ void k_cursor() {
    int t = blockIdx.x * blockDim.x + threadIdx.x;
    if (t < 2 * NN) {
        int r = t / NN, i = t - r * NN;
        g_cur[r][i] = g_rowptr[r][i];
    }
}

__global__ void k_scatter(const int* __restrict__ s1, const int* __restrict__ d1,
                          const int* __restrict__ s2, const int* __restrict__ d2) {
    int e = blockIdx.x * blockDim.x + threadIdx.x;
    int r = blockIdx.y;
    if (e >= EE) return;
    const int* S = r ? s2 : s1;
    const int* Dd = r ? d2 : d1;
    int d = Dd[e];
    int pos = atomicAdd(&g_cur[r][d], 1);
    g_csrc[r][pos] = S[e];
}

// ---------------- node-centric softmax + gather ----------------
__global__ void __launch_bounds__(256) k_node() {
    int gw = (blockIdx.x * 256 + threadIdx.x) >> 5;
    int lane = threadIdx.x & 31;
    int r = blockIdx.y;
    int n = gw;
    if (n >= NN) return;
    int start = g_rowptr[r][n], end = g_rowptr[r][n + 1];
    const float* el = g_el[r];
    float4 er4 = *(const float4*)(&g_er[r][n * NH]);
    const int* csrc = g_csrc[r];
    const float* feat = r ? g_feat1 : g_feat0;

    float4 m = make_float4(-3.0e38f, -3.0e38f, -3.0e38f, -3.0e38f);
    for (int i = start + lane; i < end; i += 32) {
        int s = csrc[i];
        float4 e4 = *(const float4*)(el + s * NH);
        m.x = fmaxf(m.x, lrelu(e4.x + er4.x));
        m.y = fmaxf(m.y, lrelu(e4.y + er4.y));
        m.z = fmaxf(m.z, lrelu(e4.z + er4.z));
        m.w = fmaxf(m.w, lrelu(e4.w + er4.w));
    }
#pragma unroll
    for (int s = 16; s >= 1; s >>= 1) {
        m.x = fmaxf(m.x, __shfl_xor_sync(0xffffffffu, m.x, s));
        m.y = fmaxf(m.y, __shfl_xor_sync(0xffffffffu, m.y, s));
        m.z = fmaxf(m.z, __shfl_xor_sync(0xffffffffu, m.z, s));
        m.w = fmaxf(m.w, __shfl_xor_sync(0xffffffffu, m.w, s));
    }
    float4 dn = make_float4(0.f, 0.f, 0.f, 0.f);
    for (int i = start + lane; i < end; i += 32) {
        int s = csrc[i];
        float4 e4 = *(const float4*)(el + s * NH);
        dn.x += __expf(lrelu(e4.x + er4.x) - m.x);
        dn.y += __expf(lrelu(e4.y + er4.y) - m.y);
        dn.z += __expf(lrelu(e4.z + er4.z) - m.z);
        dn.w += __expf(lrelu(e4.w + er4.w) - m.w);
    }
#pragma unroll
    for (int s = 16; s >= 1; s >>= 1) {
        dn.x += __shfl_xor_sync(0xffffffffu, dn.x, s);
        dn.y += __shfl_xor_sync(0xffffffffu, dn.y, s);
        dn.z += __shfl_xor_sync(0xffffffffu, dn.z, s);
        dn.w += __shfl_xor_sync(0xffffffffu, dn.w, s);
    }
    float4 inv = make_float4(dn.x > 0.f ? 1.f / dn.x : 0.f,
                             dn.y > 0.f ? 1.f / dn.y : 0.f,
                             dn.z > 0.f ? 1.f / dn.z : 0.f,
                             dn.w > 0.f ? 1.f / dn.w : 0.f);
    int head = lane >> 3;
    float erh = pick4(er4, head);
    float mh = pick4(m, head);
    float ih = pick4(inv, head);
    float acc[8] = {0.f, 0.f, 0.f, 0.f, 0.f, 0.f, 0.f, 0.f};
    for (int i = start; i < end; i++) {
        int s = csrc[i];
        float4 e4 = *(const float4*)(el + s * NH);
        float a = __expf(lrelu(pick4(e4, head) + erh) - mh) * ih;
        const float* f = feat + (size_t)s * HD + lane * 8;
        float4 f0 = *(const float4*)f, f1 = *(const float4*)(f + 4);
        acc[0] += a * f0.x; acc[1] += a * f0.y; acc[2] += a * f0.z; acc[3] += a * f0.w;
        acc[4] += a * f1.x; acc[5] += a * f1.y; acc[6] += a * f1.z; acc[7] += a * f1.w;
    }
    float* o = (r ? g_o1 : g_o0) + (size_t)n * HD + lane * 8;
    *(float4*)o = make_float4(acc[0], acc[1], acc[2], acc[3]);
    *(float4*)(o + 4) = make_float4(acc[4], acc[5], acc[6], acc[7]);
}

// ---------------- launch ----------------
extern "C" void kernel_launch(void* const* d_in, const int* in_sizes, int n_in,
                              void* d_out, int out_size) {
    const float* h   = (const float*)d_in[0];
    const float* Wg1 = (const float*)d_in[1];
    const float* al1 = (const float*)d_in[2];
    const float* ar1 = (const float*)d_in[3];
    const float* b1  = (const float*)d_in[4];
    const float* Wg2 = (const float*)d_in[5];
    const float* al2 = (const float*)d_in[6];
    const float* ar2 = (const float*)d_in[7];
    const float* b2  = (const float*)d_in[8];
    const float* Wfc = (const float*)d_in[9];
    const float* bfc = (const float*)d_in[10];
    const int* src1  = (const int*)d_in[11];
    const int* dst1  = (const int*)d_in[12];
    const int* src2  = (const int*)d_in[13];
    const int* dst2  = (const int*)d_in[14];
    float* out = (float*)d_out;

    k_zero<<<(2 * NN + 255) / 256, 256>>>();
    k_bfc<<<1, 256>>>(b1, b2, Wfc, bfc);

    dim3 g1(4, (NN + 127) / 128);
    k_gemm1<<<g1, 128>>>(h, Wg1, Wg2, al1, ar1, al2, ar2);

    dim3 ge((EE + 255) / 256, 2);
    k_count<<<ge, 256>>>(dst1, dst2);
    k_scan<<<2, 1024>>>();
    k_cursor<<<(2 * NN + 255) / 256, 256>>>();
    k_scatter<<<ge, 256>>>(src1, dst1, src2, dst2);

    dim3 gn((NN + 7) / 8, 2);
    k_node<<<gn, 256>>>();

    dim3 g2(2, (NN + 127) / 128);
    k_gemm2<<<g2, 128>>>(Wfc, out);
}